// round 12
// baseline (speedup 1.0000x reference)
#include <cuda_runtime.h>
#include <cuda_fp16.h>
#include <cstdint>
#include <math.h>

#define BB 32
#define NN 128
#define OBSD 32
#define HD 128
#define MD 128
#define NLAYERS 3
#define ROWS (BB*NN)      // 4096
#define TRE 16            // rows/block: encoder
#define TRU 8             // rows/block: pairproj / upd (R10 config)
#define IPB 4             // i-nodes per pair block

// ---------------- scratch (static device globals; no allocation) -----------
__device__ float g_z[ROWS*HD];
__device__ float g_A[ROWS*MD];
// Bp interleaved: per batch [f/2][j][f&1]  (64 x 128 x 2 floats)
__device__ float g_BpI[BB*64*NN*2];
__device__ float g_S[ROWS*MD];
__device__ __align__(16) __half g_W[NLAYERS*MD*MD];   // w2^T fp16 [l][m][k]

__device__ __forceinline__ uint32_t smem_u32(const void* p) {
    uint32_t a;
    asm("{ .reg .u64 t; cvta.to.shared.u64 t, %1; cvt.u32.u64 %0, t; }" : "=r"(a) : "l"(p));
    return a;
}

// ---------------- encoder: obs(4096x32) -> H -> H -> H --------------------
__global__ void enc_kernel(const float* __restrict__ obs,
                           const float* __restrict__ w1, const float* __restrict__ b1,
                           const float* __restrict__ w2, const float* __restrict__ b2,
                           const float* __restrict__ w3, const float* __restrict__ b3)
{
    __shared__ float s_in[TRE][OBSD];
    __shared__ float s_h[TRE][HD];
    __shared__ float s_h2[TRE][HD];
    const int c = threadIdx.x;
    const int row0 = blockIdx.x * TRE;

    for (int idx = c; idx < TRE*OBSD; idx += HD)
        s_in[idx / OBSD][idx % OBSD] = obs[row0*OBSD + idx];
    __syncthreads();

    float acc[TRE];
#pragma unroll
    for (int r = 0; r < TRE; r++) acc[r] = b1[c];
    for (int k = 0; k < OBSD; k++) {
        float wv = w1[k*HD + c];
#pragma unroll
        for (int r = 0; r < TRE; r++) acc[r] += s_in[r][k]*wv;
    }
#pragma unroll
    for (int r = 0; r < TRE; r++) s_h[r][c] = fmaxf(acc[r], 0.f);
    __syncthreads();

#pragma unroll
    for (int r = 0; r < TRE; r++) acc[r] = b2[c];
    for (int k = 0; k < HD; k++) {
        float wv = w2[k*HD + c];
#pragma unroll
        for (int r = 0; r < TRE; r++) acc[r] += s_h[r][k]*wv;
    }
#pragma unroll
    for (int r = 0; r < TRE; r++) s_h2[r][c] = fmaxf(acc[r], 0.f);
    __syncthreads();

#pragma unroll
    for (int r = 0; r < TRE; r++) acc[r] = b3[c];
    for (int k = 0; k < HD; k++) {
        float wv = w3[k*HD + c];
#pragma unroll
        for (int r = 0; r < TRE; r++) acc[r] += s_h2[r][k]*wv;
    }
#pragma unroll
    for (int r = 0; r < TRE; r++) g_z[(row0+r)*HD + c] = acc[r];
}

// -------- per-node projections, split-k over 2 thread halves --------
__global__ void __launch_bounds__(256) pairproj_kernel(const float* __restrict__ w1,
                                                       const float* __restrict__ b1)
{
    __shared__ float s_z[TRU][HD];
    __shared__ float sPA[TRU][128];
    __shared__ float sPB[TRU][128];
    const int tid = threadIdx.x;
    const int c  = tid & 127;
    const int kh = tid >> 7;
    const int row0 = blockIdx.x * TRU;

    for (int idx = tid; idx < TRU*HD; idx += 256)
        ((float*)s_z)[idx] = g_z[row0*HD + idx];
    __syncthreads();

    float accA[TRU], accB[TRU];
#pragma unroll
    for (int r = 0; r < TRU; r++) { accA[r] = 0.f; accB[r] = 0.f; }
    const int k0 = kh*64;
#pragma unroll 4
    for (int k = k0; k < k0 + 64; k++) {
        float wa = w1[k*MD + c];
        float wb = w1[(HD + k)*MD + c];
#pragma unroll
        for (int r = 0; r < TRU; r++) {
            float zv = s_z[r][k];
            accA[r] += zv*wa;
            accB[r] += zv*wb;
        }
    }
    if (kh == 1) {
#pragma unroll
        for (int r = 0; r < TRU; r++) { sPA[r][c] = accA[r]; sPB[r][c] = accB[r]; }
    }
    __syncthreads();
    if (kh == 0) {
        const int b  = row0 / NN;
        const int j0 = row0 % NN;
        float bias = b1[c];
        const int fp = c >> 1, e = c & 1;
#pragma unroll
        for (int r = 0; r < TRU; r++) {
            g_A[(row0+r)*MD + c] = accA[r] + sPA[r][c] + bias;
            // interleaved: [b][fp][j][e]
            g_BpI[((size_t)b*64 + fp)*256 + (j0+r)*2 + e] = accB[r] + sPB[r][c];
        }
    }
}

// -------- prep (all layers): w2 (fp32 [k][m]) -> w2^T fp16 [l][m][k] -------
__global__ void prep_w2_all(const float* __restrict__ msg_w2)
{
    int l = blockIdx.y;
    int e = blockIdx.x * 128 + threadIdx.x;   // 16384 elems per layer
    int m = e >> 7, k = e & 127;
    g_W[(size_t)l*MD*MD + m*MD + k] =
        __float2half(msg_w2[(size_t)l*MD*MD + k*MD + m]);
}

// ======================= pair kernel (mma.sync fp16 + ldmatrix) =============
// R7 tiling: 4 j-groups (32 rows) x 2 m-groups (64 cols). IPB=4 i/block.
// Software-pipelined: H1 double-buffered; build(i+1) overlaps MMA/epilogue(i).
#define PADH 136                 // halves per row (272 B)
#define ROWB (PADH*2)            // 272
#define TILE_BYTES (128*ROWB)    // 34816
#define OFF_W    0
#define OFF_H1A  TILE_BYTES
#define OFF_H1B  (2*TILE_BYTES)
#define OFF_AUX  (3*TILE_BYTES)
// aux: sA 4*128f | dsh 4*128f | sW1d 128f | b2s 128f | red 4*128f
#define AUX_SA   0
#define AUX_D    2048
#define AUX_W1D  4096
#define AUX_B2   4608
#define AUX_RED  5120
#define SMEM_PAIR (OFF_AUX + 5120 + 2048)

__device__ __forceinline__ void mma_f16(float c[4], uint32_t a0, uint32_t a1,
                                        uint32_t a2, uint32_t a3,
                                        uint32_t b0, uint32_t b1) {
    asm volatile(
        "mma.sync.aligned.m16n8k16.row.col.f32.f16.f16.f32 "
        "{%0,%1,%2,%3}, {%4,%5,%6,%7}, {%8,%9}, {%0,%1,%2,%3};"
        : "+f"(c[0]), "+f"(c[1]), "+f"(c[2]), "+f"(c[3])
        : "r"(a0), "r"(a1), "r"(a2), "r"(a3), "r"(b0), "r"(b1));
}
#define LDSM_X4(r0, r1, r2, r3, addr) \
    asm volatile("ldmatrix.sync.aligned.m8n8.x4.shared.b16 {%0,%1,%2,%3}, [%4];" \
        : "=r"(r0), "=r"(r1), "=r"(r2), "=r"(r3) : "r"(addr))

__global__ void __launch_bounds__(256, 2) tc_pair_kernel(
    const float* __restrict__ pos,
    const float* __restrict__ w1d,
    const float* __restrict__ b2,
    int layer)
{
    extern __shared__ __align__(16) char s[];
    float* sA   = (float*)(s + OFF_AUX + AUX_SA);
    float* dsh  = (float*)(s + OFF_AUX + AUX_D);
    float* sW1d = (float*)(s + OFF_AUX + AUX_W1D);
    float* b2s  = (float*)(s + OFF_AUX + AUX_B2);
    float* red  = (float*)(s + OFF_AUX + AUX_RED);

    const int tid  = threadIdx.x;
    const int wid  = tid >> 5;
    const int lane = tid & 31;
    const int g    = lane >> 2;
    const int tig  = lane & 3;
    const int wj   = wid & 3;         // j quarter (32 rows)
    const int wm   = wid >> 2;        // m half   (64 cols)
    const int blk  = blockIdx.x;      // 1024 blocks
    const int b    = blk >> 5;
    const int i0   = (blk & 31) * IPB;

    // ---- stage W (fp16, padded rows), once per block ----
    {
        float4* dw = (float4*)(s + OFF_W);
        const float4* sw = (const float4*)(g_W + (size_t)layer*MD*MD);
        for (int i = tid; i < 2048; i += 256) {
            int row = i >> 4, c4 = i & 15;
            dw[row*17 + c4] = sw[i];
        }
    }
    // ---- stage A rows, distances, w1d, bias ----
    for (int t = tid; t < IPB*128; t += 256) {
        int ii = t >> 7, j = t & 127;
        sA[t] = g_A[(size_t)(b*NN + i0 + ii)*MD + j];
        const float2 pi = ((const float2*)pos)[b*NN + i0 + ii];
        const float2 pj = ((const float2*)pos)[b*NN + j];
        float dx = pi.x - pj.x, dy = pi.y - pj.y;
        dsh[t] = sqrtf(dx*dx + dy*dy);
    }
    if (tid < 128) { sW1d[tid] = w1d[tid]; b2s[tid] = b2[tid]; }
    __syncthreads();

    // ---- ldmatrix bases, per H1 buffer ----
    const uint32_t sbase = smem_u32(s);
    uint32_t aAddr[2][2];
#pragma unroll
    for (int bsel = 0; bsel < 2; bsel++)
#pragma unroll
        for (int jt = 0; jt < 2; jt++)
            aAddr[bsel][jt] = sbase + OFF_H1A + (uint32_t)bsel*TILE_BYTES
                            + (uint32_t)(wj*32 + jt*16 + (lane & 15))*ROWB
                            + (uint32_t)(lane >> 4)*16;
    const int bt = lane >> 3;
    const uint32_t bW = sbase + OFF_W
                      + (uint32_t)(wm*64 + (bt >> 1)*8 + (lane & 7))*ROWB
                      + (uint32_t)(bt & 1)*16;

    // ---- H1 build constants: fixed j per thread, contiguous f-pairs ----
    const int jb   = tid & 127;        // this thread's j
    const int kh   = tid >> 7;         // f-pair half (0: fp 0..31, 1: fp 32..63)
    const float2* BpI = (const float2*)g_BpI + ((size_t)b*64 + kh*32)*128 + jb;
    uint32_t h1row[2];
#pragma unroll
    for (int bsel = 0; bsel < 2; bsel++)
        h1row[bsel] = sbase + OFF_H1A + (uint32_t)bsel*TILE_BYTES
                    + (uint32_t)jb*ROWB + (uint32_t)kh*128;

    // build H1 for node ii into buffer bsel
    auto build = [&](int ii, int bsel) {
        const float d = dsh[ii*128 + jb];
        const float* aI = sA + ii*128 + kh*64;
        const float* wI = sW1d + kh*64;
        const uint32_t h1w = h1row[bsel];
        uint32_t prev = 0;
#pragma unroll
        for (int t = 0; t < 32; t++) {
            float2 bp = BpI[t*128];            // one LDG.64 per f-pair
            int f0 = t*2;
            float v0 = fmaxf(aI[f0]   + bp.x + d*wI[f0],   0.f);
            float v1 = fmaxf(aI[f0+1] + bp.y + d*wI[f0+1], 0.f);
            __half2 hv = __floats2half2_rn(v0, v1);
            uint32_t cur = *(uint32_t*)&hv;
            if (t & 1) {
                uint2 pk = make_uint2(prev, cur);
                asm volatile("st.shared.v2.b32 [%0], {%1, %2};" ::
                    "r"(h1w + (uint32_t)(t-1)*4), "r"(pk.x), "r"(pk.y));
            } else {
                prev = cur;
            }
        }
    };

    // prologue: build H1(0) into buffer 0
    build(0, 0);
    __syncthreads();

    for (int ii = 0; ii < IPB; ii++) {
        const int cur = ii & 1;

        // ---- MMA: 32j x 64m per warp, K=128, single fp16 pass ----
        float acc[2][8][4];
#pragma unroll
        for (int jt = 0; jt < 2; jt++)
#pragma unroll
            for (int nt = 0; nt < 8; nt++)
#pragma unroll
                for (int q = 0; q < 4; q++) acc[jt][nt][q] = 0.f;

#pragma unroll
        for (int kk = 0; kk < 8; kk++) {
            uint32_t a[2][4];
            LDSM_X4(a[0][0], a[0][1], a[0][2], a[0][3], aAddr[cur][0] + kk*32);
            LDSM_X4(a[1][0], a[1][1], a[1][2], a[1][3], aAddr[cur][1] + kk*32);
#pragma unroll
            for (int p = 0; p < 4; p++) {
                uint32_t w0, w1r, w2r, w3r;
                LDSM_X4(w0, w1r, w2r, w3r, bW + kk*32 + p*(16*ROWB));
                mma_f16(acc[0][2*p],   a[0][0], a[0][1], a[0][2], a[0][3], w0,  w1r);
                mma_f16(acc[1][2*p],   a[1][0], a[1][1], a[1][2], a[1][3], w0,  w1r);
                mma_f16(acc[0][2*p+1], a[0][0], a[0][1], a[0][2], a[0][3], w2r, w3r);
                mma_f16(acc[1][2*p+1], a[1][0], a[1][1], a[1][2], a[1][3], w2r, w3r);
            }
        }

        // ---- overlapped: build next i's H1 into the other buffer ----
        if (ii + 1 < IPB) build(ii + 1, cur ^ 1);
        __syncthreads();   // H1(next) complete; epilogue may write red

        // ---- epilogue: +b2, relu, zero diag, reduce over warp's 32 j ----
        const int inode = i0 + ii;
#pragma unroll
        for (int nt = 0; nt < 8; nt++) {
            const int col0 = wm*64 + nt*8 + 2*tig;
            const float bias0 = b2s[col0], bias1 = b2s[col0 + 1];
            float s0 = 0.f, s1 = 0.f;
#pragma unroll
            for (int jt = 0; jt < 2; jt++) {
                int r0 = wj*32 + jt*16 + g;
                int r1 = r0 + 8;
                float v0 = fmaxf(acc[jt][nt][0] + bias0, 0.f);
                float v1 = fmaxf(acc[jt][nt][1] + bias1, 0.f);
                float v2 = fmaxf(acc[jt][nt][2] + bias0, 0.f);
                float v3 = fmaxf(acc[jt][nt][3] + bias1, 0.f);
                if (r0 == inode) { v0 = 0.f; v1 = 0.f; }
                if (r1 == inode) { v2 = 0.f; v3 = 0.f; }
                s0 += v0 + v2;
                s1 += v1 + v3;
            }
#pragma unroll
            for (int off = 4; off < 32; off <<= 1) {
                s0 += __shfl_xor_sync(0xffffffffu, s0, off);
                s1 += __shfl_xor_sync(0xffffffffu, s1, off);
            }
            if (g == 0) {
                red[wj*128 + col0]     = s0;
                red[wj*128 + col0 + 1] = s1;
            }
        }
        __syncthreads();   // red complete

        if (tid < 128)
            g_S[(size_t)(b*NN + inode)*MD + tid] =
                red[tid] + red[128 + tid] + red[256 + tid] + red[384 + tid];
        // S-write reads red; next epilogue's red writes are behind the next
        // iteration's post-build __syncthreads.
    }
}

// -------- update MLP, split-k over 2 thread halves --------
__global__ void __launch_bounds__(256) upd_kernel(
        const float* __restrict__ w3, const float* __restrict__ b3,
        const float* __restrict__ uw1, const float* __restrict__ ub1,
        const float* __restrict__ uw2, const float* __restrict__ ub2,
        const float* __restrict__ uw3, const float* __restrict__ ub3,
        float* __restrict__ out, int write_out)
{
    __shared__ float sS[TRU][MD];     // S, later reused as u2
    __shared__ float sZ[TRU][HD];
    __shared__ float sMsg[TRU][MD];
    __shared__ float sT[TRU][HD];
    __shared__ float sP[TRU][128];
    const int tid = threadIdx.x;
    const int c  = tid & 127;
    const int kh = tid >> 7;
    const int row0 = blockIdx.x * TRU;

    for (int idx = tid; idx < TRU*MD; idx += 256) {
        ((float*)sS)[idx] = g_S[row0*MD + idx];
        ((float*)sZ)[idx] = g_z[row0*HD + idx];
    }
    __syncthreads();

    float acc[TRU];
#pragma unroll
    for (int r = 0; r < TRU; r++) acc[r] = 0.f;
    {
        const int k0 = kh*64;
#pragma unroll 4
        for (int k = k0; k < k0 + 64; k++) {
            float wv = w3[k*MD + c];
#pragma unroll
            for (int r = 0; r < TRU; r++) acc[r] += sS[r][k]*wv;
        }
    }
    if (kh == 1) { for (int r = 0; r < TRU; r++) sP[r][c] = acc[r]; }
    __syncthreads();
    if (kh == 0) {
        float bias = 127.0f * b3[c];
        for (int r = 0; r < TRU; r++) sMsg[r][c] = acc[r] + sP[r][c] + bias;
    }
    __syncthreads();

#pragma unroll
    for (int r = 0; r < TRU; r++) acc[r] = 0.f;
    if (kh == 0) {
#pragma unroll 4
        for (int k = 0; k < HD; k++) {
            float wv = uw1[k*HD + c];
#pragma unroll
            for (int r = 0; r < TRU; r++) acc[r] += sZ[r][k]*wv;
        }
    } else {
#pragma unroll 4
        for (int k = 0; k < MD; k++) {
            float wv = uw1[(HD + k)*HD + c];
#pragma unroll
            for (int r = 0; r < TRU; r++) acc[r] += sMsg[r][k]*wv;
        }
    }
    if (kh == 1) { for (int r = 0; r < TRU; r++) sP[r][c] = acc[r]; }
    __syncthreads();
    if (kh == 0) {
        float bias = ub1[c];
        for (int r = 0; r < TRU; r++) sT[r][c] = fmaxf(acc[r] + sP[r][c] + bias, 0.f);
    }
    __syncthreads();

#pragma unroll
    for (int r = 0; r < TRU; r++) acc[r] = 0.f;
    {
        const int k0 = kh*64;
#pragma unroll 4
        for (int k = k0; k < k0 + 64; k++) {
            float wv = uw2[k*HD + c];
#pragma unroll
            for (int r = 0; r < TRU; r++) acc[r] += sT[r][k]*wv;
        }
    }
    if (kh == 1) { for (int r = 0; r < TRU; r++) sP[r][c] = acc[r]; }
    __syncthreads();
    if (kh == 0) {
        float bias = ub2[c];
        for (int r = 0; r < TRU; r++) sS[r][c] = fmaxf(acc[r] + sP[r][c] + bias, 0.f);
    }
    __syncthreads();

#pragma unroll
    for (int r = 0; r < TRU; r++) acc[r] = 0.f;
    {
        const int k0 = kh*64;
#pragma unroll 4
        for (int k = k0; k < k0 + 64; k++) {
            float wv = uw3[k*HD + c];
#pragma unroll
            for (int r = 0; r < TRU; r++) acc[r] += sS[r][k]*wv;
        }
    }
    if (kh == 1) { for (int r = 0; r < TRU; r++) sP[r][c] = acc[r]; }
    __syncthreads();
    if (kh == 0) {
        float bias = ub3[c];
        if (write_out) {
            for (int r = 0; r < TRU; r++) out[(row0+r)*HD + c] = acc[r] + sP[r][c] + bias;
        } else {
            for (int r = 0; r < TRU; r++) g_z[(row0+r)*HD + c] = acc[r] + sP[r][c] + bias;
        }
    }
}

extern "C" void kernel_launch(void* const* d_in, const int* in_sizes, int n_in,
                              void* d_out, int out_size)
{
    const float* obs    = (const float*)d_in[0];
    const float* pos    = (const float*)d_in[1];
    const float* enc_w1 = (const float*)d_in[2];
    const float* enc_b1 = (const float*)d_in[3];
    const float* enc_w2 = (const float*)d_in[4];
    const float* enc_b2 = (const float*)d_in[5];
    const float* enc_w3 = (const float*)d_in[6];
    const float* enc_b3 = (const float*)d_in[7];
    const float* msg_w1 = (const float*)d_in[8];
    const float* msg_b1 = (const float*)d_in[9];
    const float* msg_w2 = (const float*)d_in[10];
    const float* msg_b2 = (const float*)d_in[11];
    const float* msg_w3 = (const float*)d_in[12];
    const float* msg_b3 = (const float*)d_in[13];
    const float* upd_w1 = (const float*)d_in[14];
    const float* upd_b1 = (const float*)d_in[15];
    const float* upd_w2 = (const float*)d_in[16];
    const float* upd_b2 = (const float*)d_in[17];
    const float* upd_w3 = (const float*)d_in[18];
    const float* upd_b3 = (const float*)d_in[19];
    float* out = (float*)d_out;

    cudaFuncSetAttribute(tc_pair_kernel,
                         cudaFuncAttributeMaxDynamicSharedMemorySize, SMEM_PAIR);

    enc_kernel<<<ROWS/TRE, HD>>>(obs, enc_w1, enc_b1, enc_w2, enc_b2, enc_w3, enc_b3);
    prep_w2_all<<<dim3(128, NLAYERS), 128>>>(msg_w2);

    for (int l = 0; l < NLAYERS; l++) {
        const float* w1 = msg_w1 + (size_t)l*(2*HD+1)*MD;
        const float* b1 = msg_b1 + (size_t)l*MD;
        const float* b2 = msg_b2 + (size_t)l*MD;
        const float* w3 = msg_w3 + (size_t)l*MD*MD;
        const float* b3 = msg_b3 + (size_t)l*MD;
        const float* uw1 = upd_w1 + (size_t)l*(HD+MD)*HD;
        const float* ub1 = upd_b1 + (size_t)l*HD;
        const float* uw2 = upd_w2 + (size_t)l*HD*HD;
        const float* ub2 = upd_b2 + (size_t)l*HD;
        const float* uw3 = upd_w3 + (size_t)l*HD*HD;
        const float* ub3 = upd_b3 + (size_t)l*HD;

        pairproj_kernel<<<ROWS/TRU, 256>>>(w1, b1);
        tc_pair_kernel<<<ROWS/IPB, 256, SMEM_PAIR>>>(pos, w1 + 2*HD*MD, b2, l);
        upd_kernel<<<ROWS/TRU, 256>>>(w3, b3, uw1, ub1, uw2, ub2, uw3, ub3,
                                      out, (l == NLAYERS-1) ? 1 : 0);
    }
}

// round 13
// speedup vs baseline: 1.0896x; 1.0896x over previous
#include <cuda_runtime.h>
#include <cuda_fp16.h>
#include <cstdint>
#include <math.h>

#define BB 32
#define NN 128
#define OBSD 32
#define HD 128
#define MD 128
#define NLAYERS 3
#define ROWS (BB*NN)      // 4096
#define TRE 16            // rows/block: encoder
#define TRU 8             // rows/block: pairproj / upd
#define IPB 4             // i-nodes per pair block

// ---------------- scratch (static device globals; no allocation) -----------
__device__ float g_z[ROWS*HD];
__device__ float g_A[ROWS*MD];
// Bp interleaved: per batch [f/2][j][f&1]  (64 x 128 x 2 floats)
__device__ float g_BpI[BB*64*NN*2];
__device__ float g_S[ROWS*MD];
__device__ __align__(16) __half g_W[NLAYERS*MD*MD];   // w2^T fp16 [l][m][k]

__device__ __forceinline__ uint32_t smem_u32(const void* p) {
    uint32_t a;
    asm("{ .reg .u64 t; cvta.to.shared.u64 t, %1; cvt.u32.u64 %0, t; }" : "=r"(a) : "l"(p));
    return a;
}

// ---------------- encoder: obs(4096x32) -> H -> H -> H --------------------
__global__ void enc_kernel(const float* __restrict__ obs,
                           const float* __restrict__ w1, const float* __restrict__ b1,
                           const float* __restrict__ w2, const float* __restrict__ b2,
                           const float* __restrict__ w3, const float* __restrict__ b3)
{
    __shared__ float s_in[TRE][OBSD];
    __shared__ float s_h[TRE][HD];
    __shared__ float s_h2[TRE][HD];
    const int c = threadIdx.x;
    const int row0 = blockIdx.x * TRE;

    for (int idx = c; idx < TRE*OBSD; idx += HD)
        s_in[idx / OBSD][idx % OBSD] = obs[row0*OBSD + idx];
    __syncthreads();

    float acc[TRE];
#pragma unroll
    for (int r = 0; r < TRE; r++) acc[r] = b1[c];
    for (int k = 0; k < OBSD; k++) {
        float wv = w1[k*HD + c];
#pragma unroll
        for (int r = 0; r < TRE; r++) acc[r] += s_in[r][k]*wv;
    }
#pragma unroll
    for (int r = 0; r < TRE; r++) s_h[r][c] = fmaxf(acc[r], 0.f);
    __syncthreads();

#pragma unroll
    for (int r = 0; r < TRE; r++) acc[r] = b2[c];
    for (int k = 0; k < HD; k++) {
        float wv = w2[k*HD + c];
#pragma unroll
        for (int r = 0; r < TRE; r++) acc[r] += s_h[r][k]*wv;
    }
#pragma unroll
    for (int r = 0; r < TRE; r++) s_h2[r][c] = fmaxf(acc[r], 0.f);
    __syncthreads();

#pragma unroll
    for (int r = 0; r < TRE; r++) acc[r] = b3[c];
    for (int k = 0; k < HD; k++) {
        float wv = w3[k*HD + c];
#pragma unroll
        for (int r = 0; r < TRE; r++) acc[r] += s_h2[r][k]*wv;
    }
#pragma unroll
    for (int r = 0; r < TRE; r++) g_z[(row0+r)*HD + c] = acc[r];
}

// -------- per-node projections (layer 0), split-k over 2 thread halves -----
__global__ void __launch_bounds__(256) pairproj_kernel(const float* __restrict__ w1,
                                                       const float* __restrict__ b1)
{
    __shared__ float s_z[TRU][HD];
    __shared__ float sPA[TRU][128];
    __shared__ float sPB[TRU][128];
    const int tid = threadIdx.x;
    const int c  = tid & 127;
    const int kh = tid >> 7;
    const int row0 = blockIdx.x * TRU;

    for (int idx = tid; idx < TRU*HD; idx += 256)
        ((float*)s_z)[idx] = g_z[row0*HD + idx];
    __syncthreads();

    float accA[TRU], accB[TRU];
#pragma unroll
    for (int r = 0; r < TRU; r++) { accA[r] = 0.f; accB[r] = 0.f; }
    const int k0 = kh*64;
#pragma unroll 4
    for (int k = k0; k < k0 + 64; k++) {
        float wa = w1[k*MD + c];
        float wb = w1[(HD + k)*MD + c];
#pragma unroll
        for (int r = 0; r < TRU; r++) {
            float zv = s_z[r][k];
            accA[r] += zv*wa;
            accB[r] += zv*wb;
        }
    }
    if (kh == 1) {
#pragma unroll
        for (int r = 0; r < TRU; r++) { sPA[r][c] = accA[r]; sPB[r][c] = accB[r]; }
    }
    __syncthreads();
    if (kh == 0) {
        const int b  = row0 / NN;
        const int j0 = row0 % NN;
        float bias = b1[c];
        const int fp = c >> 1, e = c & 1;
#pragma unroll
        for (int r = 0; r < TRU; r++) {
            g_A[(row0+r)*MD + c] = accA[r] + sPA[r][c] + bias;
            // interleaved: [b][fp][j][e]
            g_BpI[((size_t)b*64 + fp)*256 + (j0+r)*2 + e] = accB[r] + sPB[r][c];
        }
    }
}

// -------- prep (all layers): w2 (fp32 [k][m]) -> w2^T fp16 [l][m][k] -------
__global__ void prep_w2_all(const float* __restrict__ msg_w2)
{
    int l = blockIdx.y;
    int e = blockIdx.x * 128 + threadIdx.x;   // 16384 elems per layer
    int m = e >> 7, k = e & 127;
    g_W[(size_t)l*MD*MD + m*MD + k] =
        __float2half(msg_w2[(size_t)l*MD*MD + k*MD + m]);
}

// ======================= pair kernel (mma.sync fp16 + ldmatrix) =============
// R10 structure: single H1 buffer, 4 j-groups x 2 m-groups, IPB=4 i/block.
#define PADH 136                 // halves per row (272 B)
#define ROWB (PADH*2)            // 272
#define TILE_BYTES (128*ROWB)    // 34816
#define OFF_W    0
#define OFF_H1   TILE_BYTES
#define OFF_AUX  (2*TILE_BYTES)
// aux: sA 4*128f | dsh 4*128f | sW1d 128f | b2s 128f | red 4*128f
#define AUX_SA   0
#define AUX_D    2048
#define AUX_W1D  4096
#define AUX_B2   4608
#define AUX_RED  5120
#define SMEM_PAIR (OFF_AUX + 5120 + 2048)

__device__ __forceinline__ void mma_f16(float c[4], uint32_t a0, uint32_t a1,
                                        uint32_t a2, uint32_t a3,
                                        uint32_t b0, uint32_t b1) {
    asm volatile(
        "mma.sync.aligned.m16n8k16.row.col.f32.f16.f16.f32 "
        "{%0,%1,%2,%3}, {%4,%5,%6,%7}, {%8,%9}, {%0,%1,%2,%3};"
        : "+f"(c[0]), "+f"(c[1]), "+f"(c[2]), "+f"(c[3])
        : "r"(a0), "r"(a1), "r"(a2), "r"(a3), "r"(b0), "r"(b1));
}
#define LDSM_X4(r0, r1, r2, r3, addr) \
    asm volatile("ldmatrix.sync.aligned.m8n8.x4.shared.b16 {%0,%1,%2,%3}, [%4];" \
        : "=r"(r0), "=r"(r1), "=r"(r2), "=r"(r3) : "r"(addr))

__global__ void __launch_bounds__(256, 2) tc_pair_kernel(
    const float* __restrict__ pos,
    const float* __restrict__ w1d,
    const float* __restrict__ b2,
    int layer)
{
    extern __shared__ __align__(16) char s[];
    float* sA   = (float*)(s + OFF_AUX + AUX_SA);
    float* dsh  = (float*)(s + OFF_AUX + AUX_D);
    float* sW1d = (float*)(s + OFF_AUX + AUX_W1D);
    float* b2s  = (float*)(s + OFF_AUX + AUX_B2);
    float* red  = (float*)(s + OFF_AUX + AUX_RED);

    const int tid  = threadIdx.x;
    const int wid  = tid >> 5;
    const int lane = tid & 31;
    const int g    = lane >> 2;
    const int tig  = lane & 3;
    const int wj   = wid & 3;         // j quarter (32 rows)
    const int wm   = wid >> 2;        // m half   (64 cols)
    const int blk  = blockIdx.x;      // 1024 blocks
    const int b    = blk >> 5;
    const int i0   = (blk & 31) * IPB;

    // ---- stage W (fp16, padded rows), once per block ----
    {
        float4* dw = (float4*)(s + OFF_W);
        const float4* sw = (const float4*)(g_W + (size_t)layer*MD*MD);
        for (int i = tid; i < 2048; i += 256) {
            int row = i >> 4, c4 = i & 15;
            dw[row*17 + c4] = sw[i];
        }
    }
    // ---- stage A rows, distances, w1d, bias ----
    for (int t = tid; t < IPB*128; t += 256) {
        int ii = t >> 7, j = t & 127;
        sA[t] = g_A[(size_t)(b*NN + i0 + ii)*MD + j];
        const float2 pi = ((const float2*)pos)[b*NN + i0 + ii];
        const float2 pj = ((const float2*)pos)[b*NN + j];
        float dx = pi.x - pj.x, dy = pi.y - pj.y;
        dsh[t] = sqrtf(dx*dx + dy*dy);
    }
    if (tid < 128) { sW1d[tid] = w1d[tid]; b2s[tid] = b2[tid]; }
    __syncthreads();

    // ---- ldmatrix bases ----
    const uint32_t sbase = smem_u32(s);
    uint32_t aAddr[2];
#pragma unroll
    for (int jt = 0; jt < 2; jt++)
        aAddr[jt] = sbase + OFF_H1 + (uint32_t)(wj*32 + jt*16 + (lane & 15))*ROWB
                  + (uint32_t)(lane >> 4)*16;
    const int bt = lane >> 3;
    const uint32_t bW = sbase + OFF_W
                      + (uint32_t)(wm*64 + (bt >> 1)*8 + (lane & 7))*ROWB
                      + (uint32_t)(bt & 1)*16;

    // ---- H1 build constants: fixed j per thread, contiguous f-pairs ----
    const int jb   = tid & 127;        // this thread's j
    const int kh   = tid >> 7;         // f-pair half (0: fp 0..31, 1: fp 32..63)
    const float2* BpI = (const float2*)g_BpI + ((size_t)b*64 + kh*32)*128 + jb;
    const uint32_t h1row = sbase + OFF_H1 + (uint32_t)jb*ROWB + (uint32_t)kh*128;

    for (int ii = 0; ii < IPB; ii++) {
        // ---- build H1[j][k] = relu(A[k] + Bp[k,j] + d[j]*w1d[k]) -> fp16 ----
        {
            const float d = dsh[ii*128 + jb];
            const float* aI = sA + ii*128 + kh*64;
            const float* wI = sW1d + kh*64;
            uint32_t prev = 0;
#pragma unroll
            for (int t = 0; t < 32; t++) {
                float2 bp = BpI[t*128];            // one LDG.64 per f-pair
                int f0 = t*2;
                float v0 = fmaxf(aI[f0]   + bp.x + d*wI[f0],   0.f);
                float v1 = fmaxf(aI[f0+1] + bp.y + d*wI[f0+1], 0.f);
                __half2 hv = __floats2half2_rn(v0, v1);
                uint32_t cur = *(uint32_t*)&hv;
                if (t & 1) {
                    uint2 pk = make_uint2(prev, cur);
                    asm volatile("st.shared.v2.b32 [%0], {%1, %2};" ::
                        "r"(h1row + (uint32_t)(t-1)*4), "r"(pk.x), "r"(pk.y));
                } else {
                    prev = cur;
                }
            }
        }
        __syncthreads();

        // ---- MMA: 32j x 64m per warp, K=128, single fp16 pass ----
        float acc[2][8][4];
#pragma unroll
        for (int jt = 0; jt < 2; jt++)
#pragma unroll
            for (int nt = 0; nt < 8; nt++)
#pragma unroll
                for (int q = 0; q < 4; q++) acc[jt][nt][q] = 0.f;

#pragma unroll
        for (int kk = 0; kk < 8; kk++) {
            uint32_t a[2][4];
            LDSM_X4(a[0][0], a[0][1], a[0][2], a[0][3], aAddr[0] + kk*32);
            LDSM_X4(a[1][0], a[1][1], a[1][2], a[1][3], aAddr[1] + kk*32);
#pragma unroll
            for (int p = 0; p < 4; p++) {
                uint32_t w0, w1r, w2r, w3r;
                LDSM_X4(w0, w1r, w2r, w3r, bW + kk*32 + p*(16*ROWB));
                mma_f16(acc[0][2*p],   a[0][0], a[0][1], a[0][2], a[0][3], w0,  w1r);
                mma_f16(acc[1][2*p],   a[1][0], a[1][1], a[1][2], a[1][3], w0,  w1r);
                mma_f16(acc[0][2*p+1], a[0][0], a[0][1], a[0][2], a[0][3], w2r, w3r);
                mma_f16(acc[1][2*p+1], a[1][0], a[1][1], a[1][2], a[1][3], w2r, w3r);
            }
        }

        // ---- epilogue: +b2, relu, zero diag, reduce over warp's 32 j ----
        const int inode = i0 + ii;
#pragma unroll
        for (int nt = 0; nt < 8; nt++) {
            const int col0 = wm*64 + nt*8 + 2*tig;
            const float bias0 = b2s[col0], bias1 = b2s[col0 + 1];
            float s0 = 0.f, s1 = 0.f;
#pragma unroll
            for (int jt = 0; jt < 2; jt++) {
                int r0 = wj*32 + jt*16 + g;
                int r1 = r0 + 8;
                float v0 = fmaxf(acc[jt][nt][0] + bias0, 0.f);
                float v1 = fmaxf(acc[jt][nt][1] + bias1, 0.f);
                float v2 = fmaxf(acc[jt][nt][2] + bias0, 0.f);
                float v3 = fmaxf(acc[jt][nt][3] + bias1, 0.f);
                if (r0 == inode) { v0 = 0.f; v1 = 0.f; }
                if (r1 == inode) { v2 = 0.f; v3 = 0.f; }
                s0 += v0 + v2;
                s1 += v1 + v3;
            }
#pragma unroll
            for (int off = 4; off < 32; off <<= 1) {
                s0 += __shfl_xor_sync(0xffffffffu, s0, off);
                s1 += __shfl_xor_sync(0xffffffffu, s1, off);
            }
            if (g == 0) {
                red[wj*128 + col0]     = s0;
                red[wj*128 + col0 + 1] = s1;
            }
        }
        __syncthreads();

        if (tid < 128)
            g_S[(size_t)(b*NN + inode)*MD + tid] =
                red[tid] + red[128 + tid] + red[256 + tid] + red[384 + tid];
        // red reads complete before next epilogue writes (guarded by the
        // post-H1-build __syncthreads of the next iteration).
    }
}

// -------- update MLP (+ fused pairproj for the NEXT layer) ------------------
__global__ void __launch_bounds__(256) upd_kernel(
        const float* __restrict__ w3, const float* __restrict__ b3,
        const float* __restrict__ uw1, const float* __restrict__ ub1,
        const float* __restrict__ uw2, const float* __restrict__ ub2,
        const float* __restrict__ uw3, const float* __restrict__ ub3,
        const float* __restrict__ w1n, const float* __restrict__ b1n,
        float* __restrict__ out, int write_out)
{
    __shared__ float sS[TRU][MD];     // S, later reused as u2
    __shared__ float sZ[TRU][HD];
    __shared__ float sMsg[TRU][MD];
    __shared__ float sT[TRU][HD];
    __shared__ float sP[TRU][128];
    const int tid = threadIdx.x;
    const int c  = tid & 127;
    const int kh = tid >> 7;
    const int row0 = blockIdx.x * TRU;

    for (int idx = tid; idx < TRU*MD; idx += 256) {
        ((float*)sS)[idx] = g_S[row0*MD + idx];
        ((float*)sZ)[idx] = g_z[row0*HD + idx];
    }
    __syncthreads();

    float acc[TRU];
#pragma unroll
    for (int r = 0; r < TRU; r++) acc[r] = 0.f;
    {
        const int k0 = kh*64;
#pragma unroll 4
        for (int k = k0; k < k0 + 64; k++) {
            float wv = w3[k*MD + c];
#pragma unroll
            for (int r = 0; r < TRU; r++) acc[r] += sS[r][k]*wv;
        }
    }
    if (kh == 1) { for (int r = 0; r < TRU; r++) sP[r][c] = acc[r]; }
    __syncthreads();
    if (kh == 0) {
        float bias = 127.0f * b3[c];
        for (int r = 0; r < TRU; r++) sMsg[r][c] = acc[r] + sP[r][c] + bias;
    }
    __syncthreads();

#pragma unroll
    for (int r = 0; r < TRU; r++) acc[r] = 0.f;
    if (kh == 0) {
#pragma unroll 4
        for (int k = 0; k < HD; k++) {
            float wv = uw1[k*HD + c];
#pragma unroll
            for (int r = 0; r < TRU; r++) acc[r] += sZ[r][k]*wv;
        }
    } else {
#pragma unroll 4
        for (int k = 0; k < MD; k++) {
            float wv = uw1[(HD + k)*HD + c];
#pragma unroll
            for (int r = 0; r < TRU; r++) acc[r] += sMsg[r][k]*wv;
        }
    }
    if (kh == 1) { for (int r = 0; r < TRU; r++) sP[r][c] = acc[r]; }
    __syncthreads();
    if (kh == 0) {
        float bias = ub1[c];
        for (int r = 0; r < TRU; r++) sT[r][c] = fmaxf(acc[r] + sP[r][c] + bias, 0.f);
    }
    __syncthreads();

#pragma unroll
    for (int r = 0; r < TRU; r++) acc[r] = 0.f;
    {
        const int k0 = kh*64;
#pragma unroll 4
        for (int k = k0; k < k0 + 64; k++) {
            float wv = uw2[k*HD + c];
#pragma unroll
            for (int r = 0; r < TRU; r++) acc[r] += sT[r][k]*wv;
        }
    }
    if (kh == 1) { for (int r = 0; r < TRU; r++) sP[r][c] = acc[r]; }
    __syncthreads();
    if (kh == 0) {
        float bias = ub2[c];
        for (int r = 0; r < TRU; r++) sS[r][c] = fmaxf(acc[r] + sP[r][c] + bias, 0.f);
    }
    __syncthreads();

#pragma unroll
    for (int r = 0; r < TRU; r++) acc[r] = 0.f;
    {
        const int k0 = kh*64;
#pragma unroll 4
        for (int k = k0; k < k0 + 64; k++) {
            float wv = uw3[k*HD + c];
#pragma unroll
            for (int r = 0; r < TRU; r++) acc[r] += sS[r][k]*wv;
        }
    }
    if (kh == 1) { for (int r = 0; r < TRU; r++) sP[r][c] = acc[r]; }
    __syncthreads();
    if (kh == 0) {
        float bias = ub3[c];
        if (write_out) {
            for (int r = 0; r < TRU; r++) out[(row0+r)*HD + c] = acc[r] + sP[r][c] + bias;
        } else {
            for (int r = 0; r < TRU; r++) {
                float zv = acc[r] + sP[r][c] + bias;
                g_z[(row0+r)*HD + c] = zv;
                sZ[r][c] = zv;                 // z_new for fused pairproj
            }
        }
    }

    // ---- fused pairproj for NEXT layer (identical math to pairproj_kernel) --
    if (!write_out) {
        __syncthreads();    // sZ = z_new visible to all

        float accA[TRU], accB[TRU];
#pragma unroll
        for (int r = 0; r < TRU; r++) { accA[r] = 0.f; accB[r] = 0.f; }
        const int k0 = kh*64;
#pragma unroll 4
        for (int k = k0; k < k0 + 64; k++) {
            float wa = w1n[k*MD + c];
            float wb = w1n[(HD + k)*MD + c];
#pragma unroll
            for (int r = 0; r < TRU; r++) {
                float zv = sZ[r][k];
                accA[r] += zv*wa;
                accB[r] += zv*wb;
            }
        }
        if (kh == 1) {
#pragma unroll
            for (int r = 0; r < TRU; r++) { sT[r][c] = accA[r]; sP[r][c] = accB[r]; }
        }
        __syncthreads();
        if (kh == 0) {
            const int b  = row0 / NN;
            const int j0 = row0 % NN;
            float bias = b1n[c];
            const int fp = c >> 1, e = c & 1;
#pragma unroll
            for (int r = 0; r < TRU; r++) {
                g_A[(row0+r)*MD + c] = accA[r] + sT[r][c] + bias;
                g_BpI[((size_t)b*64 + fp)*256 + (j0+r)*2 + e] = accB[r] + sP[r][c];
            }
        }
    }
}

extern "C" void kernel_launch(void* const* d_in, const int* in_sizes, int n_in,
                              void* d_out, int out_size)
{
    const float* obs    = (const float*)d_in[0];
    const float* pos    = (const float*)d_in[1];
    const float* enc_w1 = (const float*)d_in[2];
    const float* enc_b1 = (const float*)d_in[3];
    const float* enc_w2 = (const float*)d_in[4];
    const float* enc_b2 = (const float*)d_in[5];
    const float* enc_w3 = (const float*)d_in[6];
    const float* enc_b3 = (const float*)d_in[7];
    const float* msg_w1 = (const float*)d_in[8];
    const float* msg_b1 = (const float*)d_in[9];
    const float* msg_w2 = (const float*)d_in[10];
    const float* msg_b2 = (const float*)d_in[11];
    const float* msg_w3 = (const float*)d_in[12];
    const float* msg_b3 = (const float*)d_in[13];
    const float* upd_w1 = (const float*)d_in[14];
    const float* upd_b1 = (const float*)d_in[15];
    const float* upd_w2 = (const float*)d_in[16];
    const float* upd_b2 = (const float*)d_in[17];
    const float* upd_w3 = (const float*)d_in[18];
    const float* upd_b3 = (const float*)d_in[19];
    float* out = (float*)d_out;

    cudaFuncSetAttribute(tc_pair_kernel,
                         cudaFuncAttributeMaxDynamicSharedMemorySize, SMEM_PAIR);

    enc_kernel<<<ROWS/TRE, HD>>>(obs, enc_w1, enc_b1, enc_w2, enc_b2, enc_w3, enc_b3);
    prep_w2_all<<<dim3(128, NLAYERS), 128>>>(msg_w2);
    pairproj_kernel<<<ROWS/TRU, 256>>>(msg_w1, msg_b1);   // layer 0

    for (int l = 0; l < NLAYERS; l++) {
        const float* w1 = msg_w1 + (size_t)l*(2*HD+1)*MD;
        const float* b2 = msg_b2 + (size_t)l*MD;
        const float* w3 = msg_w3 + (size_t)l*MD*MD;
        const float* b3 = msg_b3 + (size_t)l*MD;
        const float* uw1 = upd_w1 + (size_t)l*(HD+MD)*HD;
        const float* ub1 = upd_b1 + (size_t)l*HD;
        const float* uw2 = upd_w2 + (size_t)l*HD*HD;
        const float* ub2 = upd_b2 + (size_t)l*HD;
        const float* uw3 = upd_w3 + (size_t)l*HD*HD;
        const float* ub3 = upd_b3 + (size_t)l*HD;
        const int last = (l == NLAYERS-1);
        const float* w1n = msg_w1 + (size_t)(l+1)*(2*HD+1)*MD;
        const float* b1n = msg_b1 + (size_t)(l+1)*MD;

        tc_pair_kernel<<<ROWS/IPB, 256, SMEM_PAIR>>>(pos, w1 + 2*HD*MD, b2, l);
        upd_kernel<<<ROWS/TRU, 256>>>(w3, b3, uw1, ub1, uw2, ub2, uw3, ub3,
                                      last ? msg_w1 : w1n, last ? msg_b1 : b1n,
                                      out, last ? 1 : 0);
    }
}

// round 14
// speedup vs baseline: 1.1283x; 1.0355x over previous
#include <cuda_runtime.h>
#include <cuda_fp16.h>
#include <cstdint>
#include <math.h>

#define BB 32
#define NN 128
#define OBSD 32
#define HD 128
#define MD 128
#define NLAYERS 3
#define ROWS (BB*NN)      // 4096
#define TRE 16            // rows/block: encoder
#define TRU 8             // rows/block: pairproj / upd
#define IPB 4             // i-nodes per pair block

// ---------------- scratch (static device globals; no allocation) -----------
__device__ float g_z[ROWS*HD];
__device__ float g_A[ROWS*MD];
// Bp interleaved: per batch [f/2][j][f&1]  (64 x 128 x 2 floats)
__device__ float g_BpI[BB*64*NN*2];
__device__ float g_S[ROWS*MD];
__device__ __align__(16) __half g_W[NLAYERS*MD*MD];   // w2^T fp16 [l][m][k]

__device__ __forceinline__ uint32_t smem_u32(const void* p) {
    uint32_t a;
    asm("{ .reg .u64 t; cvta.to.shared.u64 t, %1; cvt.u32.u64 %0, t; }" : "=r"(a) : "l"(p));
    return a;
}

// ---------------- encoder: obs(4096x32) -> H -> H -> H --------------------
__global__ void enc_kernel(const float* __restrict__ obs,
                           const float* __restrict__ w1, const float* __restrict__ b1,
                           const float* __restrict__ w2, const float* __restrict__ b2,
                           const float* __restrict__ w3, const float* __restrict__ b3)
{
    __shared__ float s_in[TRE][OBSD];
    __shared__ float s_h[TRE][HD];
    __shared__ float s_h2[TRE][HD];
    const int c = threadIdx.x;
    const int row0 = blockIdx.x * TRE;

    for (int idx = c; idx < TRE*OBSD; idx += HD)
        s_in[idx / OBSD][idx % OBSD] = obs[row0*OBSD + idx];
    __syncthreads();

    float acc[TRE];
#pragma unroll
    for (int r = 0; r < TRE; r++) acc[r] = b1[c];
    for (int k = 0; k < OBSD; k++) {
        float wv = w1[k*HD + c];
#pragma unroll
        for (int r = 0; r < TRE; r++) acc[r] += s_in[r][k]*wv;
    }
#pragma unroll
    for (int r = 0; r < TRE; r++) s_h[r][c] = fmaxf(acc[r], 0.f);
    __syncthreads();

#pragma unroll
    for (int r = 0; r < TRE; r++) acc[r] = b2[c];
    for (int k = 0; k < HD; k++) {
        float wv = w2[k*HD + c];
#pragma unroll
        for (int r = 0; r < TRE; r++) acc[r] += s_h[r][k]*wv;
    }
#pragma unroll
    for (int r = 0; r < TRE; r++) s_h2[r][c] = fmaxf(acc[r], 0.f);
    __syncthreads();

#pragma unroll
    for (int r = 0; r < TRE; r++) acc[r] = b3[c];
    for (int k = 0; k < HD; k++) {
        float wv = w3[k*HD + c];
#pragma unroll
        for (int r = 0; r < TRE; r++) acc[r] += s_h2[r][k]*wv;
    }
#pragma unroll
    for (int r = 0; r < TRE; r++) g_z[(row0+r)*HD + c] = acc[r];
}

// -------- per-node projections, split-k over 2 thread halves --------
__global__ void __launch_bounds__(256) pairproj_kernel(const float* __restrict__ w1,
                                                       const float* __restrict__ b1)
{
    __shared__ float s_z[TRU][HD];
    __shared__ float sPA[TRU][128];
    __shared__ float sPB[TRU][128];
    const int tid = threadIdx.x;
    const int c  = tid & 127;
    const int kh = tid >> 7;
    const int row0 = blockIdx.x * TRU;

    for (int idx = tid; idx < TRU*HD; idx += 256)
        ((float*)s_z)[idx] = g_z[row0*HD + idx];
    __syncthreads();

    float accA[TRU], accB[TRU];
#pragma unroll
    for (int r = 0; r < TRU; r++) { accA[r] = 0.f; accB[r] = 0.f; }
    const int k0 = kh*64;
#pragma unroll 4
    for (int k = k0; k < k0 + 64; k++) {
        float wa = w1[k*MD + c];
        float wb = w1[(HD + k)*MD + c];
#pragma unroll
        for (int r = 0; r < TRU; r++) {
            float zv = s_z[r][k];
            accA[r] += zv*wa;
            accB[r] += zv*wb;
        }
    }
    if (kh == 1) {
#pragma unroll
        for (int r = 0; r < TRU; r++) { sPA[r][c] = accA[r]; sPB[r][c] = accB[r]; }
    }
    __syncthreads();
    if (kh == 0) {
        const int b  = row0 / NN;
        const int j0 = row0 % NN;
        float bias = b1[c];
        const int fp = c >> 1, e = c & 1;
#pragma unroll
        for (int r = 0; r < TRU; r++) {
            g_A[(row0+r)*MD + c] = accA[r] + sPA[r][c] + bias;
            // interleaved: [b][fp][j][e]
            g_BpI[((size_t)b*64 + fp)*256 + (j0+r)*2 + e] = accB[r] + sPB[r][c];
        }
    }
}

// -------- prep (all layers): w2 (fp32 [k][m]) -> w2^T fp16 [l][m][k] -------
__global__ void prep_w2_all(const float* __restrict__ msg_w2)
{
    int l = blockIdx.y;
    int e = blockIdx.x * 128 + threadIdx.x;   // 16384 elems per layer
    int m = e >> 7, k = e & 127;
    g_W[(size_t)l*MD*MD + m*MD + k] =
        __float2half(msg_w2[(size_t)l*MD*MD + k*MD + m]);
}

// ======================= pair kernel (mma.sync fp16 + ldmatrix) =============
// R10 tiling (4 j-groups x 2 m-groups, IPB=4), but i-PAIRED schedule:
//   build(i)+build(i+1) | bar | MMA(i),epi(i)->red0, MMA(i+1),epi(i+1)->red1
//   | bar | S-write(i)+S-write(i+1).      (1 barrier per i instead of 2)
#define PADH 136                 // halves per row (272 B)
#define ROWB (PADH*2)            // 272
#define TILE_BYTES (128*ROWB)    // 34816
#define OFF_W    0
#define OFF_H1A  TILE_BYTES
#define OFF_H1B  (2*TILE_BYTES)
#define OFF_AUX  (3*TILE_BYTES)
// aux: sA 4*128f | dsh 4*128f | sW1d 128f | b2s 128f | red0 4*128f | red1 4*128f
#define AUX_SA   0
#define AUX_D    2048
#define AUX_W1D  4096
#define AUX_B2   4608
#define AUX_RED  5120
#define SMEM_PAIR (OFF_AUX + 5120 + 4096)

__device__ __forceinline__ void mma_f16(float c[4], uint32_t a0, uint32_t a1,
                                        uint32_t a2, uint32_t a3,
                                        uint32_t b0, uint32_t b1) {
    asm volatile(
        "mma.sync.aligned.m16n8k16.row.col.f32.f16.f16.f32 "
        "{%0,%1,%2,%3}, {%4,%5,%6,%7}, {%8,%9}, {%0,%1,%2,%3};"
        : "+f"(c[0]), "+f"(c[1]), "+f"(c[2]), "+f"(c[3])
        : "r"(a0), "r"(a1), "r"(a2), "r"(a3), "r"(b0), "r"(b1));
}
#define LDSM_X4(r0, r1, r2, r3, addr) \
    asm volatile("ldmatrix.sync.aligned.m8n8.x4.shared.b16 {%0,%1,%2,%3}, [%4];" \
        : "=r"(r0), "=r"(r1), "=r"(r2), "=r"(r3) : "r"(addr))

__global__ void __launch_bounds__(256, 2) tc_pair_kernel(
    const float* __restrict__ pos,
    const float* __restrict__ w1d,
    const float* __restrict__ b2,
    int layer)
{
    extern __shared__ __align__(16) char s[];
    float* sA   = (float*)(s + OFF_AUX + AUX_SA);
    float* dsh  = (float*)(s + OFF_AUX + AUX_D);
    float* sW1d = (float*)(s + OFF_AUX + AUX_W1D);
    float* b2s  = (float*)(s + OFF_AUX + AUX_B2);
    float* red  = (float*)(s + OFF_AUX + AUX_RED);   // red0 | red1 (512 f each)

    const int tid  = threadIdx.x;
    const int wid  = tid >> 5;
    const int lane = tid & 31;
    const int g    = lane >> 2;
    const int tig  = lane & 3;
    const int wj   = wid & 3;         // j quarter (32 rows)
    const int wm   = wid >> 2;        // m half   (64 cols)
    const int blk  = blockIdx.x;      // 1024 blocks
    const int b    = blk >> 5;
    const int i0   = (blk & 31) * IPB;

    // ---- stage W (fp16, padded rows), once per block ----
    {
        float4* dw = (float4*)(s + OFF_W);
        const float4* sw = (const float4*)(g_W + (size_t)layer*MD*MD);
        for (int i = tid; i < 2048; i += 256) {
            int row = i >> 4, c4 = i & 15;
            dw[row*17 + c4] = sw[i];
        }
    }
    // ---- stage A rows, distances, w1d, bias ----
    for (int t = tid; t < IPB*128; t += 256) {
        int ii = t >> 7, j = t & 127;
        sA[t] = g_A[(size_t)(b*NN + i0 + ii)*MD + j];
        const float2 pi = ((const float2*)pos)[b*NN + i0 + ii];
        const float2 pj = ((const float2*)pos)[b*NN + j];
        float dx = pi.x - pj.x, dy = pi.y - pj.y;
        dsh[t] = sqrtf(dx*dx + dy*dy);
    }
    if (tid < 128) { sW1d[tid] = w1d[tid]; b2s[tid] = b2[tid]; }
    __syncthreads();

    // ---- ldmatrix bases (two H1 buffers) ----
    const uint32_t sbase = smem_u32(s);
    uint32_t aAddr[2][2];
#pragma unroll
    for (int bsel = 0; bsel < 2; bsel++)
#pragma unroll
        for (int jt = 0; jt < 2; jt++)
            aAddr[bsel][jt] = sbase + OFF_H1A + (uint32_t)bsel*TILE_BYTES
                            + (uint32_t)(wj*32 + jt*16 + (lane & 15))*ROWB
                            + (uint32_t)(lane >> 4)*16;
    const int bt = lane >> 3;
    const uint32_t bW = sbase + OFF_W
                      + (uint32_t)(wm*64 + (bt >> 1)*8 + (lane & 7))*ROWB
                      + (uint32_t)(bt & 1)*16;

    // ---- H1 build constants: fixed j per thread, contiguous f-pairs ----
    const int jb   = tid & 127;        // this thread's j
    const int kh   = tid >> 7;         // f-pair half (0: fp 0..31, 1: fp 32..63)
    const float2* BpI = (const float2*)g_BpI + ((size_t)b*64 + kh*32)*128 + jb;
    uint32_t h1row[2];
#pragma unroll
    for (int bsel = 0; bsel < 2; bsel++)
        h1row[bsel] = sbase + OFF_H1A + (uint32_t)bsel*TILE_BYTES
                    + (uint32_t)jb*ROWB + (uint32_t)kh*128;

    // build H1 for node ii into buffer bsel (identical math to R10)
    auto build = [&](int ii, int bsel) {
        const float d = dsh[ii*128 + jb];
        const float* aI = sA + ii*128 + kh*64;
        const float* wI = sW1d + kh*64;
        const uint32_t h1w = h1row[bsel];
        uint32_t prev = 0;
#pragma unroll
        for (int t = 0; t < 32; t++) {
            float2 bp = BpI[t*128];            // one LDG.64 per f-pair
            int f0 = t*2;
            float v0 = fmaxf(aI[f0]   + bp.x + d*wI[f0],   0.f);
            float v1 = fmaxf(aI[f0+1] + bp.y + d*wI[f0+1], 0.f);
            __half2 hv = __floats2half2_rn(v0, v1);
            uint32_t cur = *(uint32_t*)&hv;
            if (t & 1) {
                uint2 pk = make_uint2(prev, cur);
                asm volatile("st.shared.v2.b32 [%0], {%1, %2};" ::
                    "r"(h1w + (uint32_t)(t-1)*4), "r"(pk.x), "r"(pk.y));
            } else {
                prev = cur;
            }
        }
    };

    // one MMA + epilogue for node ii from buffer bsel, writing red[half]
    auto mma_epi = [&](int ii, int bsel, int half) {
        float acc[2][8][4];
#pragma unroll
        for (int jt = 0; jt < 2; jt++)
#pragma unroll
            for (int nt = 0; nt < 8; nt++)
#pragma unroll
                for (int q = 0; q < 4; q++) acc[jt][nt][q] = 0.f;

#pragma unroll
        for (int kk = 0; kk < 8; kk++) {
            uint32_t a[2][4];
            LDSM_X4(a[0][0], a[0][1], a[0][2], a[0][3], aAddr[bsel][0] + kk*32);
            LDSM_X4(a[1][0], a[1][1], a[1][2], a[1][3], aAddr[bsel][1] + kk*32);
#pragma unroll
            for (int p = 0; p < 4; p++) {
                uint32_t w0, w1r, w2r, w3r;
                LDSM_X4(w0, w1r, w2r, w3r, bW + kk*32 + p*(16*ROWB));
                mma_f16(acc[0][2*p],   a[0][0], a[0][1], a[0][2], a[0][3], w0,  w1r);
                mma_f16(acc[1][2*p],   a[1][0], a[1][1], a[1][2], a[1][3], w0,  w1r);
                mma_f16(acc[0][2*p+1], a[0][0], a[0][1], a[0][2], a[0][3], w2r, w3r);
                mma_f16(acc[1][2*p+1], a[1][0], a[1][1], a[1][2], a[1][3], w2r, w3r);
            }
        }

        const int inode = i0 + ii;
        float* redH = red + half*512;
#pragma unroll
        for (int nt = 0; nt < 8; nt++) {
            const int col0 = wm*64 + nt*8 + 2*tig;
            const float bias0 = b2s[col0], bias1 = b2s[col0 + 1];
            float s0 = 0.f, s1 = 0.f;
#pragma unroll
            for (int jt = 0; jt < 2; jt++) {
                int r0 = wj*32 + jt*16 + g;
                int r1 = r0 + 8;
                float v0 = fmaxf(acc[jt][nt][0] + bias0, 0.f);
                float v1 = fmaxf(acc[jt][nt][1] + bias1, 0.f);
                float v2 = fmaxf(acc[jt][nt][2] + bias0, 0.f);
                float v3 = fmaxf(acc[jt][nt][3] + bias1, 0.f);
                if (r0 == inode) { v0 = 0.f; v1 = 0.f; }
                if (r1 == inode) { v2 = 0.f; v3 = 0.f; }
                s0 += v0 + v2;
                s1 += v1 + v3;
            }
#pragma unroll
            for (int off = 4; off < 32; off <<= 1) {
                s0 += __shfl_xor_sync(0xffffffffu, s0, off);
                s1 += __shfl_xor_sync(0xffffffffu, s1, off);
            }
            if (g == 0) {
                redH[wj*128 + col0]     = s0;
                redH[wj*128 + col0 + 1] = s1;
            }
        }
    };

    for (int ip = 0; ip < IPB; ip += 2) {
        // ---- build both H1 buffers (accumulators not live here) ----
        build(ip,     0);
        build(ip + 1, 1);
        __syncthreads();

        // ---- MMA + epilogue for both i's (no barrier between) ----
        mma_epi(ip,     0, 0);
        mma_epi(ip + 1, 1, 1);
        __syncthreads();

        // ---- S-writes for both ----
        if (tid < 128) {
            g_S[(size_t)(b*NN + i0 + ip)*MD + tid] =
                red[tid] + red[128 + tid] + red[256 + tid] + red[384 + tid];
            const float* r1 = red + 512;
            g_S[(size_t)(b*NN + i0 + ip + 1)*MD + tid] =
                r1[tid] + r1[128 + tid] + r1[256 + tid] + r1[384 + tid];
        }
        // next pair's builds overwrite H1 buffers; all warps passed the
        // post-mma_epi barrier, so no warp still reads them. red is re-written
        // only after the next pair's post-build barrier.
    }
}

// -------- update MLP, split-k over 2 thread halves --------
__global__ void __launch_bounds__(256) upd_kernel(
        const float* __restrict__ w3, const float* __restrict__ b3,
        const float* __restrict__ uw1, const float* __restrict__ ub1,
        const float* __restrict__ uw2, const float* __restrict__ ub2,
        const float* __restrict__ uw3, const float* __restrict__ ub3,
        float* __restrict__ out, int write_out)
{
    __shared__ float sS[TRU][MD];     // S, later reused as u2
    __shared__ float sZ[TRU][HD];
    __shared__ float sMsg[TRU][MD];
    __shared__ float sT[TRU][HD];
    __shared__ float sP[TRU][128];
    const int tid = threadIdx.x;
    const int c  = tid & 127;
    const int kh = tid >> 7;
    const int row0 = blockIdx.x * TRU;

    for (int idx = tid; idx < TRU*MD; idx += 256) {
        ((float*)sS)[idx] = g_S[row0*MD + idx];
        ((float*)sZ)[idx] = g_z[row0*HD + idx];
    }
    __syncthreads();

    float acc[TRU];
#pragma unroll
    for (int r = 0; r < TRU; r++) acc[r] = 0.f;
    {
        const int k0 = kh*64;
#pragma unroll 4
        for (int k = k0; k < k0 + 64; k++) {
            float wv = w3[k*MD + c];
#pragma unroll
            for (int r = 0; r < TRU; r++) acc[r] += sS[r][k]*wv;
        }
    }
    if (kh == 1) { for (int r = 0; r < TRU; r++) sP[r][c] = acc[r]; }
    __syncthreads();
    if (kh == 0) {
        float bias = 127.0f * b3[c];
        for (int r = 0; r < TRU; r++) sMsg[r][c] = acc[r] + sP[r][c] + bias;
    }
    __syncthreads();

#pragma unroll
    for (int r = 0; r < TRU; r++) acc[r] = 0.f;
    if (kh == 0) {
#pragma unroll 4
        for (int k = 0; k < HD; k++) {
            float wv = uw1[k*HD + c];
#pragma unroll
            for (int r = 0; r < TRU; r++) acc[r] += sZ[r][k]*wv;
        }
    } else {
#pragma unroll 4
        for (int k = 0; k < MD; k++) {
            float wv = uw1[(HD + k)*HD + c];
#pragma unroll
            for (int r = 0; r < TRU; r++) acc[r] += sMsg[r][k]*wv;
        }
    }
    if (kh == 1) { for (int r = 0; r < TRU; r++) sP[r][c] = acc[r]; }
    __syncthreads();
    if (kh == 0) {
        float bias = ub1[c];
        for (int r = 0; r < TRU; r++) sT[r][c] = fmaxf(acc[r] + sP[r][c] + bias, 0.f);
    }
    __syncthreads();

#pragma unroll
    for (int r = 0; r < TRU; r++) acc[r] = 0.f;
    {
        const int k0 = kh*64;
#pragma unroll 4
        for (int k = k0; k < k0 + 64; k++) {
            float wv = uw2[k*HD + c];
#pragma unroll
            for (int r = 0; r < TRU; r++) acc[r] += sT[r][k]*wv;
        }
    }
    if (kh == 1) { for (int r = 0; r < TRU; r++) sP[r][c] = acc[r]; }
    __syncthreads();
    if (kh == 0) {
        float bias = ub2[c];
        for (int r = 0; r < TRU; r++) sS[r][c] = fmaxf(acc[r] + sP[r][c] + bias, 0.f);
    }
    __syncthreads();

#pragma unroll
    for (int r = 0; r < TRU; r++) acc[r] = 0.f;
    {
        const int k0 = kh*64;
#pragma unroll 4
        for (int k = k0; k < k0 + 64; k++) {
            float wv = uw3[k*HD + c];
#pragma unroll
            for (int r = 0; r < TRU; r++) acc[r] += sS[r][k]*wv;
        }
    }
    if (kh == 1) { for (int r = 0; r < TRU; r++) sP[r][c] = acc[r]; }
    __syncthreads();
    if (kh == 0) {
        float bias = ub3[c];
        if (write_out) {
            for (int r = 0; r < TRU; r++) out[(row0+r)*HD + c] = acc[r] + sP[r][c] + bias;
        } else {
            for (int r = 0; r < TRU; r++) g_z[(row0+r)*HD + c] = acc[r] + sP[r][c] + bias;
        }
    }
}

extern "C" void kernel_launch(void* const* d_in, const int* in_sizes, int n_in,
                              void* d_out, int out_size)
{
    const float* obs    = (const float*)d_in[0];
    const float* pos    = (const float*)d_in[1];
    const float* enc_w1 = (const float*)d_in[2];
    const float* enc_b1 = (const float*)d_in[3];
    const float* enc_w2 = (const float*)d_in[4];
    const float* enc_b2 = (const float*)d_in[5];
    const float* enc_w3 = (const float*)d_in[6];
    const float* enc_b3 = (const float*)d_in[7];
    const float* msg_w1 = (const float*)d_in[8];
    const float* msg_b1 = (const float*)d_in[9];
    const float* msg_w2 = (const float*)d_in[10];
    const float* msg_b2 = (const float*)d_in[11];
    const float* msg_w3 = (const float*)d_in[12];
    const float* msg_b3 = (const float*)d_in[13];
    const float* upd_w1 = (const float*)d_in[14];
    const float* upd_b1 = (const float*)d_in[15];
    const float* upd_w2 = (const float*)d_in[16];
    const float* upd_b2 = (const float*)d_in[17];
    const float* upd_w3 = (const float*)d_in[18];
    const float* upd_b3 = (const float*)d_in[19];
    float* out = (float*)d_out;

    cudaFuncSetAttribute(tc_pair_kernel,
                         cudaFuncAttributeMaxDynamicSharedMemorySize, SMEM_PAIR);

    enc_kernel<<<ROWS/TRE, HD>>>(obs, enc_w1, enc_b1, enc_w2, enc_b2, enc_w3, enc_b3);
    prep_w2_all<<<dim3(128, NLAYERS), 128>>>(msg_w2);

    for (int l = 0; l < NLAYERS; l++) {
        const float* w1 = msg_w1 + (size_t)l*(2*HD+1)*MD;
        const float* b1 = msg_b1 + (size_t)l*MD;
        const float* b2 = msg_b2 + (size_t)l*MD;
        const float* w3 = msg_w3 + (size_t)l*MD*MD;
        const float* b3 = msg_b3 + (size_t)l*MD;
        const float* uw1 = upd_w1 + (size_t)l*(HD+MD)*HD;
        const float* ub1 = upd_b1 + (size_t)l*HD;
        const float* uw2 = upd_w2 + (size_t)l*HD*HD;
        const float* ub2 = upd_b2 + (size_t)l*HD;
        const float* uw3 = upd_w3 + (size_t)l*HD*HD;
        const float* ub3 = upd_b3 + (size_t)l*HD;

        pairproj_kernel<<<ROWS/TRU, 256>>>(w1, b1);
        tc_pair_kernel<<<ROWS/IPB, 256, SMEM_PAIR>>>(pos, w1 + 2*HD*MD, b2, l);
        upd_kernel<<<ROWS/TRU, 256>>>(w3, b3, uw1, ub1, uw2, ub2, uw3, ub3,
                                      out, (l == NLAYERS-1) ? 1 : 0);
    }
}